// round 7
// baseline (speedup 1.0000x reference)
#include <cuda_runtime.h>
#include <cstdint>

// DigitCaps dynamic routing, fused.
// b_t[i,j] = u_hat[b,i,j,:] . Vsum_t[b,j,:], Vsum_t = sum_{tau<t} v_tau
// W prepacked to [chunk][g][e][dpair][j] with g-stride 644 ulls
// (bank-shift 8 per g -> truly conflict-free LDS.64).
// ONE cp.async.bulk per chunk, 3-slot ring. 256-thr blocks, 2 blocks/SM.

#define B_      512
#define NI      1152
#define NJ      10
#define DI      8
#define DO      16

#define THREADS 256
#define BT      8        // batches per block (4 pairs)
#define G_      6        // i's per chunk
#define ISPLITS 8
#define ICHUNK  144      // NI / ISPLITS
#define NCHUNK  24       // ICHUNK / G_
#define NCHUNK_TOTAL (ISPLITS * NCHUNK)   // 192
#define NPART   ISPLITS  // 8 partials per (b,j)

// W smem layout per chunk: [g][e][k][j] ull, g-stride padded to 644
#define WTILE_ULL  644                    // 640 data + 4 pad (bank shift 8/g)
#define WBUF_ULL   (G_ * WTILE_ULL)       // 3864 ull per ring slot
#define WBUF       (WBUF_ULL * 2)         // 7728 words
#define NBUF    3
#define VROW    18
#define CHUNK_BYTES (WBUF * 4)            // 30912 (16B multiple)
#define SMEM_WORDS (NBUF * WBUF + BT * NJ * VROW + 8)   // 23184+1440+8 = 24632

__device__ float g_wpad[(size_t)NCHUNK_TOTAL * WBUF];      // ~5.9 MB padded W image
__device__ float g_partial[(size_t)B_ * NPART * NJ * DO];
__device__ float g_vsum[B_ * NJ * DO];

using ull = unsigned long long;

__device__ __forceinline__ ull fma2(ull a, ull b, ull c) {
    ull d; asm("fma.rn.f32x2 %0, %1, %2, %3;" : "=l"(d) : "l"(a), "l"(b), "l"(c)); return d;
}
__device__ __forceinline__ ull bcast2(float x) {
    ull d; asm("mov.b64 %0, {%1, %1};" : "=l"(d) : "f"(x)); return d;
}
__device__ __forceinline__ ull pack2(float x, float y) {
    ull d; asm("mov.b64 %0, {%1, %2};" : "=l"(d) : "f"(x), "f"(y)); return d;
}
__device__ __forceinline__ float sum2(ull a) {
    float l, h; asm("mov.b64 {%0, %1}, %2;" : "=f"(l), "=f"(h) : "l"(a)); return l + h;
}
__device__ __forceinline__ void st2(float* p, ull v) { *(ull*)p = v; }

__device__ __forceinline__ void mbar_init(uint32_t addr, uint32_t count) {
    asm volatile("mbarrier.init.shared.b64 [%0], %1;" :: "r"(addr), "r"(count) : "memory");
}
__device__ __forceinline__ void mbar_wait(uint32_t addr, uint32_t parity) {
    asm volatile(
        "{\n\t.reg .pred P;\n\t"
        "WL_%=:\n\t"
        "mbarrier.try_wait.parity.acquire.cta.shared::cta.b64 P, [%0], %1, 0x989680;\n\t"
        "@P bra.uni WD_%=;\n\t"
        "bra.uni WL_%=;\n\t"
        "WD_%=:\n\t}"
        :: "r"(addr), "r"(parity) : "memory");
}

// ONE bulk copy per chunk: prepacked tile image -> ring slot.
__device__ __forceinline__ void issue_chunk(int chunk, int slot,
                                            uint32_t sbase, uint32_t mbase, int tid) {
    if (tid == 0) {
        uint32_t mbar = mbase + slot * 8;
        asm volatile("mbarrier.arrive.expect_tx.shared.b64 _, [%0], %1;"
                     :: "r"(mbar), "r"((uint32_t)CHUNK_BYTES) : "memory");
        const float* src = g_wpad + (size_t)chunk * WBUF;
        uint32_t dst = sbase + (uint32_t)(slot * WBUF) * 4;
        asm volatile(
            "cp.async.bulk.shared::cluster.global.mbarrier::complete_tx::bytes "
            "[%0], [%1], %2, [%3];"
            :: "r"(dst), "l"(src), "r"((uint32_t)CHUNK_BYTES), "r"(mbar) : "memory");
    }
}

// W[i][j][e][d] -> g_wpad ull[chunk*WBUF_ULL + g*644 + e*80 + k*10 + j]
__global__ void prepack_kernel(const float* __restrict__ W) {
    int t = blockIdx.x * blockDim.x + threadIdx.x;   // one (i,j,e)
    if (t >= NI * NJ * DI) return;
    int e = t % DI;
    int r = t / DI;
    int j = r % NJ;
    int i = r / NJ;
    int chunk = i / G_;
    int g = i - chunk * G_;
    const float4* src = (const float4*)(W + (((size_t)(i * NJ + j)) * DI + e) * DO);
    float4 v0 = src[0], v1 = src[1], v2 = src[2], v3 = src[3];
    ull* dst = (ull*)g_wpad + (size_t)chunk * WBUF_ULL + g * WTILE_ULL + e * 80 + j;
    dst[0]  = pack2(v0.x, v0.y);
    dst[10] = pack2(v0.z, v0.w);
    dst[20] = pack2(v1.x, v1.y);
    dst[30] = pack2(v1.z, v1.w);
    dst[40] = pack2(v2.x, v2.y);
    dst[50] = pack2(v2.z, v2.w);
    dst[60] = pack2(v3.x, v3.y);
    dst[70] = pack2(v3.z, v3.w);
}

template <bool FIRST>
__global__ void __launch_bounds__(THREADS, 2)
sweep_kernel(const float* __restrict__ u) {
    extern __shared__ float smem[];
    float* wst = smem;                       // W ring, 3 slots
    float* vsm = smem + NBUF * WBUF;         // Vsum stage (padded rows)
    float* red = smem;                       // post-loop staging (reuses ring)

    const int tid  = threadIdx.x;
    const int lane = tid & 31;
    const int warp = tid >> 5;               // 0..7
    const int seg  = lane / 10;              // 0..2 active, 3 idle
    const bool active = (seg < 3);
    const int j    = lane - seg * 10;
    const int unit = warp * 3 + (active ? seg : 0);   // 0..23
    const int bp   = unit & 3;               // 0..3
    const int g    = unit >> 2;              // 0..5

    const int c0g   = blockIdx.x * NCHUNK;
    const int i0    = blockIdx.x * ICHUNK;
    const int bbase = blockIdx.y * BT;

    uint32_t smem_base = (uint32_t)__cvta_generic_to_shared(wst);
    uint32_t mbar_base = (uint32_t)__cvta_generic_to_shared(smem + NBUF * WBUF + BT * NJ * VROW);

    if (tid == 0) {
        mbar_init(mbar_base + 0, 1);
        mbar_init(mbar_base + 8, 1);
        mbar_init(mbar_base + 16, 1);
    }
    if (!FIRST) {
        for (int idx = tid; idx < BT * NJ * DO; idx += THREADS) {
            vsm[(idx >> 4) * VROW + (idx & 15)] = g_vsum[bbase * NJ * DO + idx];
        }
    }
    __syncthreads();

    issue_chunk(c0g, 0, smem_base, mbar_base, tid);
    issue_chunk(c0g + 1, 1, smem_base, mbar_base, tid);

    ull sacc0[8], sacc1[8];
    #pragma unroll
    for (int k = 0; k < 8; k++) { sacc0[k] = 0ULL; sacc1[k] = 0ULL; }

    const int b0 = bbase + bp * 2;
    const float* u0p = u + (size_t)b0 * NI * DI;
    const float* u1p = u0p + (size_t)NI * DI;
    const float* vs0 = vsm + (bp * 2 * NJ + j) * VROW;
    const float* vs1 = vs0 + NJ * VROW;

    for (int c = 0; c < NCHUNK; c++) {
        const int buf = c % NBUF;
        const int i = i0 + c * G_ + g;

        float ur0[8], ur1[8];
        if (active) {
            float4 ua = *(const float4*)(u0p + (size_t)i * DI);
            float4 ub = *(const float4*)(u0p + (size_t)i * DI + 4);
            float4 uc = *(const float4*)(u1p + (size_t)i * DI);
            float4 ud = *(const float4*)(u1p + (size_t)i * DI + 4);
            ur0[0]=ua.x; ur0[1]=ua.y; ur0[2]=ua.z; ur0[3]=ua.w;
            ur0[4]=ub.x; ur0[5]=ub.y; ur0[6]=ub.z; ur0[7]=ub.w;
            ur1[0]=uc.x; ur1[1]=uc.y; ur1[2]=uc.z; ur1[3]=uc.w;
            ur1[4]=ud.x; ur1[5]=ud.y; ur1[6]=ud.z; ur1[7]=ud.w;
        }

        __syncthreads();   // all warps done with chunk c-1 -> its slot is reusable
        if (c + 2 < NCHUNK)
            issue_chunk(c0g + c + 2, (c + 2) % NBUF, smem_base, mbar_base, tid);

        mbar_wait(mbar_base + buf * 8, (c / NBUF) & 1);

        if (active) {
            const ull* wt = (const ull*)(wst + buf * WBUF) + g * WTILE_ULL + j;

            if (FIRST) {
                #pragma unroll
                for (int e = 0; e < 8; e++) {
                    const ull* wte = wt + e * 80;
                    ull ue0 = bcast2(ur0[e]);
                    ull ue1 = bcast2(ur1[e]);
                    #pragma unroll
                    for (int k = 0; k < 8; k++) {
                        ull wv = wte[k * 10];
                        sacc0[k] = fma2(ue0, wv, sacc0[k]);
                        sacc1[k] = fma2(ue1, wv, sacc1[k]);
                    }
                }
            } else {
                ull a0[8], a1[8];
                #pragma unroll
                for (int k = 0; k < 8; k++) { a0[k] = 0ULL; a1[k] = 0ULL; }
                #pragma unroll
                for (int e = 0; e < 8; e++) {
                    const ull* wte = wt + e * 80;
                    ull ue0 = bcast2(ur0[e]);
                    ull ue1 = bcast2(ur1[e]);
                    #pragma unroll
                    for (int k = 0; k < 8; k++) {
                        ull wv = wte[k * 10];
                        a0[k] = fma2(ue0, wv, a0[k]);
                        a1[k] = fma2(ue1, wv, a1[k]);
                    }
                }

                ull d0 = 0ULL, d1 = 0ULL;
                #pragma unroll
                for (int k = 0; k < 8; k++) {
                    ull v0 = ((const ull*)vs0)[k];
                    ull v1 = ((const ull*)vs1)[k];
                    d0 = fma2(a0[k], v0, d0);
                    d1 = fma2(a1[k], v1, d1);
                }
                float l0 = sum2(d0), l1 = sum2(d1);
                float e0 = __expf(l0), e1 = __expf(l1);
                float t0 = 0.f, t1 = 0.f;
                const int base = seg * 10;
                #pragma unroll
                for (int jj = 0; jj < 10; jj++) {
                    t0 += __shfl_sync(0x3FFFFFFFu, e0, base + jj);
                    t1 += __shfl_sync(0x3FFFFFFFu, e1, base + jj);
                }
                ull c0 = bcast2(__fdividef(e0, t0));
                ull c1 = bcast2(__fdividef(e1, t1));
                #pragma unroll
                for (int k = 0; k < 8; k++) {
                    sacc0[k] = fma2(c0, a0[k], sacc0[k]);
                    sacc1[k] = fma2(c1, a1[k], sacc1[k]);
                }
            }
        }
    }

    // ---- in-block reduction over g ----
    __syncthreads();
    if (active) {
        int r0 = ((bp * 6 + g) * 2 + 0) * 10 + j;
        int r1 = r0 + 10;
        #pragma unroll
        for (int k = 0; k < 8; k++) {
            st2(red + r0 * 16 + 2 * k, sacc0[k]);
            st2(red + r1 * 16 + 2 * k, sacc1[k]);
        }
    }
    __syncthreads();

    #pragma unroll 1
    for (int idx = tid; idx < BT * NJ * DO; idx += THREADS) {
        int d  = idx & 15;
        int r  = idx >> 4;
        int jj = r % 10;
        int r2 = r / 10;
        int bb = r2 & 1;
        int bpp = r2 >> 1;               // 0..3
        float s = 0.f;
        #pragma unroll
        for (int gg = 0; gg < 6; gg++)
            s += red[(((bpp * 6 + gg) * 2 + bb) * 10 + jj) * 16 + d];
        if (FIRST) s *= 0.1f;
        int b = bbase + bpp * 2 + bb;
        g_partial[((size_t)(b * NPART + blockIdx.x) * NJ + jj) * DO + d] = s;
    }
}

template <bool FIRST, bool LAST>
__global__ void reduce_kernel(float* __restrict__ out) {
    int t = blockIdx.x * blockDim.x + threadIdx.x;
    if (t >= B_ * NJ * 4) return;
    int q = t & 3;
    int j = (t >> 2) % NJ;
    int b = t / (NJ * 4);

    const float4* src = (const float4*)g_partial + ((size_t)(b * NPART) * NJ + j) * 4 + q;
    float4 acc = make_float4(0.f, 0.f, 0.f, 0.f);
    #pragma unroll
    for (int p = 0; p < NPART; p++) {
        float4 x = src[(size_t)p * NJ * 4];
        acc.x += x.x; acc.y += x.y; acc.z += x.z; acc.w += x.w;
    }

    float sq = acc.x * acc.x + acc.y * acc.y + acc.z * acc.z + acc.w * acc.w;
    sq += __shfl_xor_sync(0xFFFFFFFFu, sq, 1);
    sq += __shfl_xor_sync(0xFFFFFFFFu, sq, 2);
    float norm = sqrtf(sq);
    float factor = sq / (norm * (1.f + sq));

    float4 v = make_float4(factor * acc.x, factor * acc.y, factor * acc.z, factor * acc.w);
    if (LAST) {
        ((float4*)out)[(size_t)(b * NJ + j) * 4 + q] = v;
    } else {
        float4* vp = (float4*)g_vsum + (b * NJ + j) * 4 + q;
        if (FIRST) {
            *vp = v;
        } else {
            float4 o = *vp;
            *vp = make_float4(o.x + v.x, o.y + v.y, o.z + v.z, o.w + v.w);
        }
    }
}

extern "C" void kernel_launch(void* const* d_in, const int* in_sizes, int n_in,
                              void* d_out, int out_size) {
    const float* u = (const float*)d_in[0];
    const float* W = (const float*)d_in[1];
    float* out = (float*)d_out;

    const int smem = SMEM_WORDS * 4;   // 98528 B
    cudaFuncSetAttribute(sweep_kernel<true>,  cudaFuncAttributeMaxDynamicSharedMemorySize, smem);
    cudaFuncSetAttribute(sweep_kernel<false>, cudaFuncAttributeMaxDynamicSharedMemorySize, smem);

    dim3 grid(ISPLITS, B_ / BT);                             // 8 x 64 = 512 blocks
    const int rblocks = (B_ * NJ * 4 + 255) / 256;           // 80
    const int pthreads = NI * NJ * DI;                       // 92160
    const int pblocks = (pthreads + 255) / 256;

    prepack_kernel<<<pblocks, 256>>>(W);                      // launch 0
    sweep_kernel<true><<<grid, THREADS, smem>>>(u);           // launch 1
    reduce_kernel<true, false><<<rblocks, 256>>>(out);        // launch 2
    sweep_kernel<false><<<grid, THREADS, smem>>>(u);          // launch 3
    reduce_kernel<false, false><<<rblocks, 256>>>(out);       // launch 4
    sweep_kernel<false><<<grid, THREADS, smem>>>(u);          // launch 5  <- ncu -s 5
    reduce_kernel<false, true><<<rblocks, 256>>>(out);        // launch 6
}

// round 10
// speedup vs baseline: 1.0193x; 1.0193x over previous
#include <cuda_runtime.h>
#include <cstdint>

// DigitCaps dynamic routing, fused.
// b_t[i,j] = u_hat[b,i,j,:] . Vsum_t[b,j,:], Vsum_t = sum_{tau<t} v_tau
// W prepacked [chunk][g][e][dpair][j]; ONE cp.async.bulk per chunk;
// 3-slot ring w/ per-chunk __syncthreads (safe); 4-shfl cyclic softmax.

#define B_      512
#define NI      1152
#define NJ      10
#define DI      8
#define DO      16

#define THREADS 256
#define BT      8        // batches per block (4 pairs)
#define G_      6        // i's per chunk
#define ISPLITS 8
#define ICHUNK  144      // NI / ISPLITS
#define NCHUNK  24       // ICHUNK / G_
#define NCHUNK_TOTAL (ISPLITS * NCHUNK)   // 192
#define NPART   ISPLITS  // 8 partials per (b,j)

#define WTILE_ULL  644
#define WBUF_ULL   (G_ * WTILE_ULL)       // 3864 ull per ring slot
#define WBUF       (WBUF_ULL * 2)         // 7728 words
#define NBUF    3
#define VROW    18
#define CHUNK_BYTES (WBUF * 4)            // 30912
#define SMEM_WORDS (NBUF * WBUF + BT * NJ * VROW + 8)

__device__ float g_wpad[(size_t)NCHUNK_TOTAL * WBUF];
__device__ float g_partial[(size_t)B_ * NPART * NJ * DO];
__device__ float g_vsum[B_ * NJ * DO];

using ull = unsigned long long;

__device__ __forceinline__ ull fma2(ull a, ull b, ull c) {
    ull d; asm("fma.rn.f32x2 %0, %1, %2, %3;" : "=l"(d) : "l"(a), "l"(b), "l"(c)); return d;
}
__device__ __forceinline__ ull add2(ull a, ull b) {
    ull d; asm("add.rn.f32x2 %0, %1, %2;" : "=l"(d) : "l"(a), "l"(b)); return d;
}
__device__ __forceinline__ ull bcast2(float x) {
    ull d; asm("mov.b64 %0, {%1, %1};" : "=l"(d) : "f"(x)); return d;
}
__device__ __forceinline__ ull pack2(float x, float y) {
    ull d; asm("mov.b64 %0, {%1, %2};" : "=l"(d) : "f"(x), "f"(y)); return d;
}
__device__ __forceinline__ float sum2(ull a) {
    float l, h; asm("mov.b64 {%0, %1}, %2;" : "=f"(l), "=f"(h) : "l"(a)); return l + h;
}
__device__ __forceinline__ void st2(float* p, ull v) { *(ull*)p = v; }

__device__ __forceinline__ void mbar_init(uint32_t addr, uint32_t count) {
    asm volatile("mbarrier.init.shared.b64 [%0], %1;" :: "r"(addr), "r"(count) : "memory");
}
__device__ __forceinline__ void mbar_wait(uint32_t addr, uint32_t parity) {
    asm volatile(
        "{\n\t.reg .pred P;\n\t"
        "WL_%=:\n\t"
        "mbarrier.try_wait.parity.acquire.cta.shared::cta.b64 P, [%0], %1, 0x989680;\n\t"
        "@P bra.uni WD_%=;\n\t"
        "bra.uni WL_%=;\n\t"
        "WD_%=:\n\t}"
        :: "r"(addr), "r"(parity) : "memory");
}

// ONE bulk copy per chunk: prepacked tile image -> ring slot.
__device__ __forceinline__ void issue_chunk(int chunk, int slot,
                                            uint32_t sbase, uint32_t mbase, int tid) {
    if (tid == 0) {
        uint32_t mbar = mbase + slot * 8;
        asm volatile("mbarrier.arrive.expect_tx.shared.b64 _, [%0], %1;"
                     :: "r"(mbar), "r"((uint32_t)CHUNK_BYTES) : "memory");
        const float* src = g_wpad + (size_t)chunk * WBUF;
        uint32_t dst = sbase + (uint32_t)(slot * WBUF) * 4;
        asm volatile(
            "cp.async.bulk.shared::cluster.global.mbarrier::complete_tx::bytes "
            "[%0], [%1], %2, [%3];"
            :: "r"(dst), "l"(src), "r"((uint32_t)CHUNK_BYTES), "r"(mbar) : "memory");
    }
}

// W[i][j][e][d] -> g_wpad ull[chunk*WBUF_ULL + g*644 + e*80 + k*10 + j]
__global__ void prepack_kernel(const float* __restrict__ W) {
    int t = blockIdx.x * blockDim.x + threadIdx.x;   // one (i,j,e)
    if (t >= NI * NJ * DI) return;
    int e = t % DI;
    int r = t / DI;
    int j = r % NJ;
    int i = r / NJ;
    int chunk = i / G_;
    int g = i - chunk * G_;
    const float4* src = (const float4*)(W + (((size_t)(i * NJ + j)) * DI + e) * DO);
    float4 v0 = src[0], v1 = src[1], v2 = src[2], v3 = src[3];
    ull* dst = (ull*)g_wpad + (size_t)chunk * WBUF_ULL + g * WTILE_ULL + e * 80 + j;
    dst[0]  = pack2(v0.x, v0.y);
    dst[10] = pack2(v0.z, v0.w);
    dst[20] = pack2(v1.x, v1.y);
    dst[30] = pack2(v1.z, v1.w);
    dst[40] = pack2(v2.x, v2.y);
    dst[50] = pack2(v2.z, v2.w);
    dst[60] = pack2(v3.x, v3.y);
    dst[70] = pack2(v3.z, v3.w);
}

template <bool FIRST>
__global__ void __launch_bounds__(THREADS, 2)
sweep_kernel(const float* __restrict__ u) {
    extern __shared__ float smem[];
    float* wst = smem;                       // W ring, 3 slots
    float* vsm = smem + NBUF * WBUF;         // Vsum stage
    float* red = smem;                       // post-loop staging (reuses ring)

    const int tid  = threadIdx.x;
    const int lane = tid & 31;
    const int warp = tid >> 5;               // 0..7
    const int seg  = lane / 10;              // 0..2 active, 3 idle
    const bool active = (seg < 3);
    const int j    = lane - seg * 10;
    const int unit = warp * 3 + (active ? seg : 0);   // 0..23
    const int bp   = unit & 3;               // 0..3
    const int g    = unit >> 2;              // 0..5

    // precomputed cyclic shfl source lanes (within this seg's 10 lanes)
    const int base = seg * 10;
    const int sl5 = base + (j >= 5 ? j - 5 : j + 5);
    const int sl1 = base + (j >= 9 ? j - 9 : j + 1);
    const int sl2 = base + (j >= 8 ? j - 8 : j + 2);
    const int sl4 = base + (j >= 6 ? j - 6 : j + 4);

    const int c0g   = blockIdx.x * NCHUNK;
    const int i0    = blockIdx.x * ICHUNK;
    const int bbase = blockIdx.y * BT;

    uint32_t smem_base = (uint32_t)__cvta_generic_to_shared(wst);
    uint32_t mbar_base = (uint32_t)__cvta_generic_to_shared(smem + NBUF * WBUF + BT * NJ * VROW);

    if (tid == 0) {
        mbar_init(mbar_base + 0, 1);
        mbar_init(mbar_base + 8, 1);
        mbar_init(mbar_base + 16, 1);
    }
    if (!FIRST) {
        for (int idx = tid; idx < BT * NJ * DO; idx += THREADS) {
            vsm[(idx >> 4) * VROW + (idx & 15)] = g_vsum[bbase * NJ * DO + idx];
        }
    }
    __syncthreads();

    issue_chunk(c0g, 0, smem_base, mbar_base, tid);
    issue_chunk(c0g + 1, 1, smem_base, mbar_base, tid);

    ull sacc0[8], sacc1[8];
    #pragma unroll
    for (int k = 0; k < 8; k++) { sacc0[k] = 0ULL; sacc1[k] = 0ULL; }

    const int b0 = bbase + bp * 2;
    const float* u0p = u + (size_t)b0 * NI * DI;
    const float* u1p = u0p + (size_t)NI * DI;
    const float* vs0 = vsm + (bp * 2 * NJ + j) * VROW;
    const float* vs1 = vs0 + NJ * VROW;

    for (int c = 0; c < NCHUNK; c++) {
        const int buf = c % NBUF;
        const int i = i0 + c * G_ + g;

        float ur0[8], ur1[8];
        if (active) {
            float4 ua = *(const float4*)(u0p + (size_t)i * DI);
            float4 ub = *(const float4*)(u0p + (size_t)i * DI + 4);
            float4 uc = *(const float4*)(u1p + (size_t)i * DI);
            float4 ud = *(const float4*)(u1p + (size_t)i * DI + 4);
            ur0[0]=ua.x; ur0[1]=ua.y; ur0[2]=ua.z; ur0[3]=ua.w;
            ur0[4]=ub.x; ur0[5]=ub.y; ur0[6]=ub.z; ur0[7]=ub.w;
            ur1[0]=uc.x; ur1[1]=uc.y; ur1[2]=uc.z; ur1[3]=uc.w;
            ur1[4]=ud.x; ur1[5]=ud.y; ur1[6]=ud.z; ur1[7]=ud.w;
        }

        __syncthreads();   // all warps done with chunk c-1 -> its slot is reusable
        if (c + 2 < NCHUNK)
            issue_chunk(c0g + c + 2, (c + 2) % NBUF, smem_base, mbar_base, tid);

        mbar_wait(mbar_base + buf * 8, (c / NBUF) & 1);

        if (active) {
            const ull* wt = (const ull*)(wst + buf * WBUF) + g * WTILE_ULL + j;

            if (FIRST) {
                #pragma unroll
                for (int e = 0; e < 8; e++) {
                    const ull* wte = wt + e * 80;
                    ull ue0 = bcast2(ur0[e]);
                    ull ue1 = bcast2(ur1[e]);
                    #pragma unroll
                    for (int k = 0; k < 8; k++) {
                        ull wv = wte[k * 10];
                        sacc0[k] = fma2(ue0, wv, sacc0[k]);
                        sacc1[k] = fma2(ue1, wv, sacc1[k]);
                    }
                }
            } else {
                ull a0[8], a1[8];
                #pragma unroll
                for (int k = 0; k < 8; k++) { a0[k] = 0ULL; a1[k] = 0ULL; }
                #pragma unroll
                for (int e = 0; e < 8; e++) {
                    const ull* wte = wt + e * 80;
                    ull ue0 = bcast2(ur0[e]);
                    ull ue1 = bcast2(ur1[e]);
                    #pragma unroll
                    for (int k = 0; k < 8; k++) {
                        ull wv = wte[k * 10];
                        a0[k] = fma2(ue0, wv, a0[k]);
                        a1[k] = fma2(ue1, wv, a1[k]);
                    }
                }

                // logit = u_hat . Vsum, two chains per batch
                ull d0a = 0ULL, d0b = 0ULL, d1a = 0ULL, d1b = 0ULL;
                #pragma unroll
                for (int k = 0; k < 4; k++) {
                    d0a = fma2(a0[k],     ((const ull*)vs0)[k],     d0a);
                    d0b = fma2(a0[k + 4], ((const ull*)vs0)[k + 4], d0b);
                    d1a = fma2(a1[k],     ((const ull*)vs1)[k],     d1a);
                    d1b = fma2(a1[k + 4], ((const ull*)vs1)[k + 4], d1b);
                }
                float lg0 = sum2(add2(d0a, d0b));   // renamed: no shadowing of lane idxs
                float lg1 = sum2(add2(d1a, d1b));
                float e0 = __expf(lg0), e1 = __expf(lg1);

                // 10-lane cyclic sum in 4 shfl steps (5-fold, then +1,+2,+4)
                const unsigned M = 0x3FFFFFFFu;
                float s50 = e0 + __shfl_sync(M, e0, sl5);
                float s51 = e1 + __shfl_sync(M, e1, sl5);
                float as0 = s50 + __shfl_sync(M, s50, sl1);
                float as1 = s51 + __shfl_sync(M, s51, sl1);
                float bs0 = as0 + __shfl_sync(M, as0, sl2);
                float bs1 = as1 + __shfl_sync(M, as1, sl2);
                float t0 = bs0 + __shfl_sync(M, s50, sl4);
                float t1 = bs1 + __shfl_sync(M, s51, sl4);

                ull c0 = bcast2(__fdividef(e0, t0));
                ull c1 = bcast2(__fdividef(e1, t1));
                #pragma unroll
                for (int k = 0; k < 8; k++) {
                    sacc0[k] = fma2(c0, a0[k], sacc0[k]);
                    sacc1[k] = fma2(c1, a1[k], sacc1[k]);
                }
            }
        }
    }

    // ---- in-block reduction over g ----
    __syncthreads();
    if (active) {
        int r0 = ((bp * 6 + g) * 2 + 0) * 10 + j;
        int r1 = r0 + 10;
        #pragma unroll
        for (int k = 0; k < 8; k++) {
            st2(red + r0 * 16 + 2 * k, sacc0[k]);
            st2(red + r1 * 16 + 2 * k, sacc1[k]);
        }
    }
    __syncthreads();

    #pragma unroll 1
    for (int idx = tid; idx < BT * NJ * DO; idx += THREADS) {
        int d  = idx & 15;
        int r  = idx >> 4;
        int jj = r % 10;
        int r2 = r / 10;
        int bb = r2 & 1;
        int bpp = r2 >> 1;               // 0..3
        float s = 0.f;
        #pragma unroll
        for (int gg = 0; gg < 6; gg++)
            s += red[(((bpp * 6 + gg) * 2 + bb) * 10 + jj) * 16 + d];
        if (FIRST) s *= 0.1f;
        int b = bbase + bpp * 2 + bb;
        g_partial[((size_t)(b * NPART + blockIdx.x) * NJ + jj) * DO + d] = s;
    }
}

template <bool FIRST, bool LAST>
__global__ void reduce_kernel(float* __restrict__ out) {
    int t = blockIdx.x * blockDim.x + threadIdx.x;
    if (t >= B_ * NJ * 4) return;
    int q = t & 3;
    int j = (t >> 2) % NJ;
    int b = t / (NJ * 4);

    const float4* src = (const float4*)g_partial + ((size_t)(b * NPART) * NJ + j) * 4 + q;
    float4 acc = make_float4(0.f, 0.f, 0.f, 0.f);
    #pragma unroll
    for (int p = 0; p < NPART; p++) {
        float4 x = src[(size_t)p * NJ * 4];
        acc.x += x.x; acc.y += x.y; acc.z += x.z; acc.w += x.w;
    }

    float sq = acc.x * acc.x + acc.y * acc.y + acc.z * acc.z + acc.w * acc.w;
    sq += __shfl_xor_sync(0xFFFFFFFFu, sq, 1);
    sq += __shfl_xor_sync(0xFFFFFFFFu, sq, 2);
    float norm = sqrtf(sq);
    float factor = sq / (norm * (1.f + sq));

    float4 v = make_float4(factor * acc.x, factor * acc.y, factor * acc.z, factor * acc.w);
    if (LAST) {
        ((float4*)out)[(size_t)(b * NJ + j) * 4 + q] = v;
    } else {
        float4* vp = (float4*)g_vsum + (b * NJ + j) * 4 + q;
        if (FIRST) {
            *vp = v;
        } else {
            float4 o = *vp;
            *vp = make_float4(o.x + v.x, o.y + v.y, o.z + v.z, o.w + v.w);
        }
    }
}

extern "C" void kernel_launch(void* const* d_in, const int* in_sizes, int n_in,
                              void* d_out, int out_size) {
    const float* u = (const float*)d_in[0];
    const float* W = (const float*)d_in[1];
    float* out = (float*)d_out;

    const int smem = SMEM_WORDS * 4;
    cudaFuncSetAttribute(sweep_kernel<true>,  cudaFuncAttributeMaxDynamicSharedMemorySize, smem);
    cudaFuncSetAttribute(sweep_kernel<false>, cudaFuncAttributeMaxDynamicSharedMemorySize, smem);

    dim3 grid(ISPLITS, B_ / BT);                             // 8 x 64 = 512 blocks
    const int rblocks = (B_ * NJ * 4 + 255) / 256;           // 80
    const int pthreads = NI * NJ * DI;                       // 92160
    const int pblocks = (pthreads + 255) / 256;

    prepack_kernel<<<pblocks, 256>>>(W);                      // launch 0
    sweep_kernel<true><<<grid, THREADS, smem>>>(u);           // launch 1
    reduce_kernel<true, false><<<rblocks, 256>>>(out);        // launch 2
    sweep_kernel<false><<<grid, THREADS, smem>>>(u);          // launch 3
    reduce_kernel<false, false><<<rblocks, 256>>>(out);       // launch 4
    sweep_kernel<false><<<grid, THREADS, smem>>>(u);          // launch 5  <- ncu -s 5
    reduce_kernel<false, true><<<rblocks, 256>>>(out);        // launch 6
}

// round 11
// speedup vs baseline: 1.1341x; 1.1126x over previous
#include <cuda_runtime.h>
#include <cstdint>

// DigitCaps dynamic routing, fused.
// b_t[i,j] = u_hat[b,i,j,:] . Vsum_t[b,j,:], Vsum_t = sum_{tau<t} v_tau
// W prepacked [chunk][g][e][dpair][j]; ONE cp.async.bulk per chunk; 3-slot ring.
// FIRST sweep: 4 batches/thread (half the blocks, half per-batch W LDS return).
// non-FIRST sweeps: 2 batches/thread + 4-shfl cyclic softmax.

#define B_      512
#define NI      1152
#define NJ      10
#define DI      8
#define DO      16

#define THREADS 256
#define BT      8        // non-FIRST: batches per block
#define BTF     16       // FIRST: batches per block
#define G_      6        // i's per chunk
#define ISPLITS 8
#define ICHUNK  144      // NI / ISPLITS
#define NCHUNK  24       // ICHUNK / G_
#define NCHUNK_TOTAL (ISPLITS * NCHUNK)   // 192
#define NPART   ISPLITS  // 8 partials per (b,j)

#define WTILE_ULL  644
#define WBUF_ULL   (G_ * WTILE_ULL)       // 3864 ull per ring slot
#define WBUF       (WBUF_ULL * 2)         // 7728 words
#define NBUF    3
#define VROW    18
#define CHUNK_BYTES (WBUF * 4)            // 30912
#define SMEM_WORDS (NBUF * WBUF + BTF * NJ * VROW + 8)

__device__ float g_wpad[(size_t)NCHUNK_TOTAL * WBUF];
__device__ float g_partial[(size_t)B_ * NPART * NJ * DO];
__device__ float g_vsum[B_ * NJ * DO];

using ull = unsigned long long;

__device__ __forceinline__ ull fma2(ull a, ull b, ull c) {
    ull d; asm("fma.rn.f32x2 %0, %1, %2, %3;" : "=l"(d) : "l"(a), "l"(b), "l"(c)); return d;
}
__device__ __forceinline__ ull add2(ull a, ull b) {
    ull d; asm("add.rn.f32x2 %0, %1, %2;" : "=l"(d) : "l"(a), "l"(b)); return d;
}
__device__ __forceinline__ ull bcast2(float x) {
    ull d; asm("mov.b64 %0, {%1, %1};" : "=l"(d) : "f"(x)); return d;
}
__device__ __forceinline__ ull pack2(float x, float y) {
    ull d; asm("mov.b64 %0, {%1, %2};" : "=l"(d) : "f"(x), "f"(y)); return d;
}
__device__ __forceinline__ float sum2(ull a) {
    float l, h; asm("mov.b64 {%0, %1}, %2;" : "=f"(l), "=f"(h) : "l"(a)); return l + h;
}
__device__ __forceinline__ void st2(float* p, ull v) { *(ull*)p = v; }

__device__ __forceinline__ void mbar_init(uint32_t addr, uint32_t count) {
    asm volatile("mbarrier.init.shared.b64 [%0], %1;" :: "r"(addr), "r"(count) : "memory");
}
__device__ __forceinline__ void mbar_wait(uint32_t addr, uint32_t parity) {
    asm volatile(
        "{\n\t.reg .pred P;\n\t"
        "WL_%=:\n\t"
        "mbarrier.try_wait.parity.acquire.cta.shared::cta.b64 P, [%0], %1, 0x989680;\n\t"
        "@P bra.uni WD_%=;\n\t"
        "bra.uni WL_%=;\n\t"
        "WD_%=:\n\t}"
        :: "r"(addr), "r"(parity) : "memory");
}

// ONE bulk copy per chunk: prepacked tile image -> ring slot.
__device__ __forceinline__ void issue_chunk(int chunk, int slot,
                                            uint32_t sbase, uint32_t mbase, int tid) {
    if (tid == 0) {
        uint32_t mbar = mbase + slot * 8;
        asm volatile("mbarrier.arrive.expect_tx.shared.b64 _, [%0], %1;"
                     :: "r"(mbar), "r"((uint32_t)CHUNK_BYTES) : "memory");
        const float* src = g_wpad + (size_t)chunk * WBUF;
        uint32_t dst = sbase + (uint32_t)(slot * WBUF) * 4;
        asm volatile(
            "cp.async.bulk.shared::cluster.global.mbarrier::complete_tx::bytes "
            "[%0], [%1], %2, [%3];"
            :: "r"(dst), "l"(src), "r"((uint32_t)CHUNK_BYTES), "r"(mbar) : "memory");
    }
}

// W[i][j][e][d] -> g_wpad ull[chunk*WBUF_ULL + g*644 + e*80 + k*10 + j]
__global__ void prepack_kernel(const float* __restrict__ W) {
    int t = blockIdx.x * blockDim.x + threadIdx.x;   // one (i,j,e)
    if (t >= NI * NJ * DI) return;
    int e = t % DI;
    int r = t / DI;
    int j = r % NJ;
    int i = r / NJ;
    int chunk = i / G_;
    int g = i - chunk * G_;
    const float4* src = (const float4*)(W + (((size_t)(i * NJ + j)) * DI + e) * DO);
    float4 v0 = src[0], v1 = src[1], v2 = src[2], v3 = src[3];
    ull* dst = (ull*)g_wpad + (size_t)chunk * WBUF_ULL + g * WTILE_ULL + e * 80 + j;
    dst[0]  = pack2(v0.x, v0.y);
    dst[10] = pack2(v0.z, v0.w);
    dst[20] = pack2(v1.x, v1.y);
    dst[30] = pack2(v1.z, v1.w);
    dst[40] = pack2(v2.x, v2.y);
    dst[50] = pack2(v2.z, v2.w);
    dst[60] = pack2(v3.x, v3.y);
    dst[70] = pack2(v3.z, v3.w);
}

// ---------------- FIRST iteration: uniform c=0.1, 4 batches/thread ----------------
__global__ void __launch_bounds__(THREADS, 2)
sweep_first_kernel(const float* __restrict__ u) {
    extern __shared__ float smem[];
    float* wst = smem;
    float* red = smem;

    const int tid  = threadIdx.x;
    const int lane = tid & 31;
    const int warp = tid >> 5;
    const int seg  = lane / 10;
    const bool active = (seg < 3);
    const int j    = lane - seg * 10;
    const int unit = warp * 3 + (active ? seg : 0);   // 0..23
    const int bq   = unit & 3;                        // 0..3  (4 batches each)
    const int g    = unit >> 2;                       // 0..5

    const int c0g   = blockIdx.x * NCHUNK;
    const int i0    = blockIdx.x * ICHUNK;
    const int bbase = blockIdx.y * BTF;

    uint32_t smem_base = (uint32_t)__cvta_generic_to_shared(wst);
    uint32_t mbar_base = (uint32_t)__cvta_generic_to_shared(smem + NBUF * WBUF + BTF * NJ * VROW);

    if (tid == 0) {
        mbar_init(mbar_base + 0, 1);
        mbar_init(mbar_base + 8, 1);
        mbar_init(mbar_base + 16, 1);
    }
    __syncthreads();

    issue_chunk(c0g, 0, smem_base, mbar_base, tid);
    issue_chunk(c0g + 1, 1, smem_base, mbar_base, tid);

    ull sacc[4][8];
    #pragma unroll
    for (int b = 0; b < 4; b++)
        #pragma unroll
        for (int k = 0; k < 8; k++) sacc[b][k] = 0ULL;

    const int b0 = bbase + bq * 4;
    const float* up = u + (size_t)b0 * NI * DI;

    for (int c = 0; c < NCHUNK; c++) {
        const int buf = c % NBUF;
        const int i = i0 + c * G_ + g;

        float ur[4][8];
        if (active) {
            #pragma unroll
            for (int b = 0; b < 4; b++) {
                const float4* s = (const float4*)(up + (size_t)b * NI * DI + (size_t)i * DI);
                float4 x = s[0], y = s[1];
                ur[b][0]=x.x; ur[b][1]=x.y; ur[b][2]=x.z; ur[b][3]=x.w;
                ur[b][4]=y.x; ur[b][5]=y.y; ur[b][6]=y.z; ur[b][7]=y.w;
            }
        }

        __syncthreads();
        if (c + 2 < NCHUNK)
            issue_chunk(c0g + c + 2, (c + 2) % NBUF, smem_base, mbar_base, tid);

        mbar_wait(mbar_base + buf * 8, (c / NBUF) & 1);

        if (active) {
            const ull* wt = (const ull*)(wst + buf * WBUF) + g * WTILE_ULL + j;
            #pragma unroll
            for (int e = 0; e < 8; e++) {
                const ull* wte = wt + e * 80;
                ull ue0 = bcast2(ur[0][e]);
                ull ue1 = bcast2(ur[1][e]);
                ull ue2 = bcast2(ur[2][e]);
                ull ue3 = bcast2(ur[3][e]);
                #pragma unroll
                for (int k = 0; k < 8; k++) {
                    ull wv = wte[k * 10];
                    sacc[0][k] = fma2(ue0, wv, sacc[0][k]);
                    sacc[1][k] = fma2(ue1, wv, sacc[1][k]);
                    sacc[2][k] = fma2(ue2, wv, sacc[2][k]);
                    sacc[3][k] = fma2(ue3, wv, sacc[3][k]);
                }
            }
        }
    }

    // ---- in-block reduction over g ----
    __syncthreads();
    if (active) {
        #pragma unroll
        for (int b = 0; b < 4; b++) {
            int r = ((bq * 4 + b) * 6 + g) * 10 + j;      // [bt][g][j]
            #pragma unroll
            for (int k = 0; k < 8; k++)
                st2(red + r * 16 + 2 * k, sacc[b][k]);
        }
    }
    __syncthreads();

    #pragma unroll 1
    for (int idx = tid; idx < BTF * NJ * DO; idx += THREADS) {
        int d  = idx & 15;
        int r  = idx >> 4;
        int jj = r % 10;
        int bt = r / 10;                 // 0..15
        float s = 0.f;
        #pragma unroll
        for (int gg = 0; gg < 6; gg++)
            s += red[((bt * 6 + gg) * 10 + jj) * 16 + d];
        s *= 0.1f;
        int b = bbase + bt;
        g_partial[((size_t)(b * NPART + blockIdx.x) * NJ + jj) * DO + d] = s;
    }
}

// ---------------- non-FIRST iterations: routing sweep, 2 batches/thread ----------------
__global__ void __launch_bounds__(THREADS, 2)
sweep_kernel(const float* __restrict__ u) {
    extern __shared__ float smem[];
    float* wst = smem;
    float* vsm = smem + NBUF * WBUF;
    float* red = smem;

    const int tid  = threadIdx.x;
    const int lane = tid & 31;
    const int warp = tid >> 5;
    const int seg  = lane / 10;
    const bool active = (seg < 3);
    const int j    = lane - seg * 10;
    const int unit = warp * 3 + (active ? seg : 0);
    const int bp   = unit & 3;
    const int g    = unit >> 2;

    const int base = seg * 10;
    const int sl5 = base + (j >= 5 ? j - 5 : j + 5);
    const int sl1 = base + (j >= 9 ? j - 9 : j + 1);
    const int sl2 = base + (j >= 8 ? j - 8 : j + 2);
    const int sl4 = base + (j >= 6 ? j - 6 : j + 4);

    const int c0g   = blockIdx.x * NCHUNK;
    const int i0    = blockIdx.x * ICHUNK;
    const int bbase = blockIdx.y * BT;

    uint32_t smem_base = (uint32_t)__cvta_generic_to_shared(wst);
    uint32_t mbar_base = (uint32_t)__cvta_generic_to_shared(smem + NBUF * WBUF + BTF * NJ * VROW);

    if (tid == 0) {
        mbar_init(mbar_base + 0, 1);
        mbar_init(mbar_base + 8, 1);
        mbar_init(mbar_base + 16, 1);
    }
    for (int idx = tid; idx < BT * NJ * DO; idx += THREADS) {
        vsm[(idx >> 4) * VROW + (idx & 15)] = g_vsum[bbase * NJ * DO + idx];
    }
    __syncthreads();

    issue_chunk(c0g, 0, smem_base, mbar_base, tid);
    issue_chunk(c0g + 1, 1, smem_base, mbar_base, tid);

    ull sacc0[8], sacc1[8];
    #pragma unroll
    for (int k = 0; k < 8; k++) { sacc0[k] = 0ULL; sacc1[k] = 0ULL; }

    const int b0 = bbase + bp * 2;
    const float* u0p = u + (size_t)b0 * NI * DI;
    const float* u1p = u0p + (size_t)NI * DI;
    const float* vs0 = vsm + (bp * 2 * NJ + j) * VROW;
    const float* vs1 = vs0 + NJ * VROW;

    for (int c = 0; c < NCHUNK; c++) {
        const int buf = c % NBUF;
        const int i = i0 + c * G_ + g;

        float ur0[8], ur1[8];
        if (active) {
            float4 ua = *(const float4*)(u0p + (size_t)i * DI);
            float4 ub = *(const float4*)(u0p + (size_t)i * DI + 4);
            float4 uc = *(const float4*)(u1p + (size_t)i * DI);
            float4 ud = *(const float4*)(u1p + (size_t)i * DI + 4);
            ur0[0]=ua.x; ur0[1]=ua.y; ur0[2]=ua.z; ur0[3]=ua.w;
            ur0[4]=ub.x; ur0[5]=ub.y; ur0[6]=ub.z; ur0[7]=ub.w;
            ur1[0]=uc.x; ur1[1]=uc.y; ur1[2]=uc.z; ur1[3]=uc.w;
            ur1[4]=ud.x; ur1[5]=ud.y; ur1[6]=ud.z; ur1[7]=ud.w;
        }

        __syncthreads();
        if (c + 2 < NCHUNK)
            issue_chunk(c0g + c + 2, (c + 2) % NBUF, smem_base, mbar_base, tid);

        mbar_wait(mbar_base + buf * 8, (c / NBUF) & 1);

        if (active) {
            const ull* wt = (const ull*)(wst + buf * WBUF) + g * WTILE_ULL + j;

            ull a0[8], a1[8];
            #pragma unroll
            for (int k = 0; k < 8; k++) { a0[k] = 0ULL; a1[k] = 0ULL; }
            #pragma unroll
            for (int e = 0; e < 8; e++) {
                const ull* wte = wt + e * 80;
                ull ue0 = bcast2(ur0[e]);
                ull ue1 = bcast2(ur1[e]);
                #pragma unroll
                for (int k = 0; k < 8; k++) {
                    ull wv = wte[k * 10];
                    a0[k] = fma2(ue0, wv, a0[k]);
                    a1[k] = fma2(ue1, wv, a1[k]);
                }
            }

            ull d0a = 0ULL, d0b = 0ULL, d1a = 0ULL, d1b = 0ULL;
            #pragma unroll
            for (int k = 0; k < 4; k++) {
                d0a = fma2(a0[k],     ((const ull*)vs0)[k],     d0a);
                d0b = fma2(a0[k + 4], ((const ull*)vs0)[k + 4], d0b);
                d1a = fma2(a1[k],     ((const ull*)vs1)[k],     d1a);
                d1b = fma2(a1[k + 4], ((const ull*)vs1)[k + 4], d1b);
            }
            float lg0 = sum2(add2(d0a, d0b));
            float lg1 = sum2(add2(d1a, d1b));
            float e0 = __expf(lg0), e1 = __expf(lg1);

            const unsigned M = 0x3FFFFFFFu;
            float s50 = e0 + __shfl_sync(M, e0, sl5);
            float s51 = e1 + __shfl_sync(M, e1, sl5);
            float as0 = s50 + __shfl_sync(M, s50, sl1);
            float as1 = s51 + __shfl_sync(M, s51, sl1);
            float bs0 = as0 + __shfl_sync(M, as0, sl2);
            float bs1 = as1 + __shfl_sync(M, as1, sl2);
            float t0 = bs0 + __shfl_sync(M, s50, sl4);
            float t1 = bs1 + __shfl_sync(M, s51, sl4);

            ull c0 = bcast2(__fdividef(e0, t0));
            ull c1 = bcast2(__fdividef(e1, t1));
            #pragma unroll
            for (int k = 0; k < 8; k++) {
                sacc0[k] = fma2(c0, a0[k], sacc0[k]);
                sacc1[k] = fma2(c1, a1[k], sacc1[k]);
            }
        }
    }

    // ---- in-block reduction over g ----
    __syncthreads();
    if (active) {
        int r0 = ((bp * 6 + g) * 2 + 0) * 10 + j;
        int r1 = r0 + 10;
        #pragma unroll
        for (int k = 0; k < 8; k++) {
            st2(red + r0 * 16 + 2 * k, sacc0[k]);
            st2(red + r1 * 16 + 2 * k, sacc1[k]);
        }
    }
    __syncthreads();

    #pragma unroll 1
    for (int idx = tid; idx < BT * NJ * DO; idx += THREADS) {
        int d  = idx & 15;
        int r  = idx >> 4;
        int jj = r % 10;
        int r2 = r / 10;
        int bb = r2 & 1;
        int bpp = r2 >> 1;
        float s = 0.f;
        #pragma unroll
        for (int gg = 0; gg < 6; gg++)
            s += red[(((bpp * 6 + gg) * 2 + bb) * 10 + jj) * 16 + d];
        int b = bbase + bpp * 2 + bb;
        g_partial[((size_t)(b * NPART + blockIdx.x) * NJ + jj) * DO + d] = s;
    }
}

template <bool FIRST, bool LAST>
__global__ void reduce_kernel(float* __restrict__ out) {
    int t = blockIdx.x * blockDim.x + threadIdx.x;
    if (t >= B_ * NJ * 4) return;
    int q = t & 3;
    int j = (t >> 2) % NJ;
    int b = t / (NJ * 4);

    const float4* src = (const float4*)g_partial + ((size_t)(b * NPART) * NJ + j) * 4 + q;
    float4 acc = make_float4(0.f, 0.f, 0.f, 0.f);
    #pragma unroll
    for (int p = 0; p < NPART; p++) {
        float4 x = src[(size_t)p * NJ * 4];
        acc.x += x.x; acc.y += x.y; acc.z += x.z; acc.w += x.w;
    }

    float sq = acc.x * acc.x + acc.y * acc.y + acc.z * acc.z + acc.w * acc.w;
    sq += __shfl_xor_sync(0xFFFFFFFFu, sq, 1);
    sq += __shfl_xor_sync(0xFFFFFFFFu, sq, 2);
    float norm = sqrtf(sq);
    float factor = sq / (norm * (1.f + sq));

    float4 v = make_float4(factor * acc.x, factor * acc.y, factor * acc.z, factor * acc.w);
    if (LAST) {
        ((float4*)out)[(size_t)(b * NJ + j) * 4 + q] = v;
    } else {
        float4* vp = (float4*)g_vsum + (b * NJ + j) * 4 + q;
        if (FIRST) {
            *vp = v;
        } else {
            float4 o = *vp;
            *vp = make_float4(o.x + v.x, o.y + v.y, o.z + v.z, o.w + v.w);
        }
    }
}

extern "C" void kernel_launch(void* const* d_in, const int* in_sizes, int n_in,
                              void* d_out, int out_size) {
    const float* u = (const float*)d_in[0];
    const float* W = (const float*)d_in[1];
    float* out = (float*)d_out;

    const int smem = SMEM_WORDS * 4;
    cudaFuncSetAttribute(sweep_first_kernel, cudaFuncAttributeMaxDynamicSharedMemorySize, smem);
    cudaFuncSetAttribute(sweep_kernel,       cudaFuncAttributeMaxDynamicSharedMemorySize, smem);

    dim3 gridF(ISPLITS, B_ / BTF);                           // 8 x 32 = 256 blocks
    dim3 grid(ISPLITS, B_ / BT);                             // 8 x 64 = 512 blocks
    const int rblocks = (B_ * NJ * 4 + 255) / 256;           // 80
    const int pthreads = NI * NJ * DI;                       // 92160
    const int pblocks = (pthreads + 255) / 256;

    prepack_kernel<<<pblocks, 256>>>(W);                      // launch 0
    sweep_first_kernel<<<gridF, THREADS, smem>>>(u);          // launch 1
    reduce_kernel<true, false><<<rblocks, 256>>>(out);        // launch 2
    sweep_kernel<<<grid, THREADS, smem>>>(u);                 // launch 3
    reduce_kernel<false, false><<<rblocks, 256>>>(out);       // launch 4
    sweep_kernel<<<grid, THREADS, smem>>>(u);                 // launch 5  <- ncu -s 5
    reduce_kernel<false, true><<<rblocks, 256>>>(out);        // launch 6
}